// round 10
// baseline (speedup 1.0000x reference)
#include <cuda_runtime.h>
#include <cuda_fp16.h>
#include <mma.h>
#include <stdlib.h>
#include <math.h>

using namespace nvcuda;

#define NN 100000
#define NE 1600000
#define ETOT (NE + NN)
#define HD 64
#define FN 13
#define SLOPE_GAT 0.2f
#define SLOPE_MLP 0.01f
#define NTASK 12500            // 100000 / 8 node-groups (gat/gemm2)
#define NT16 6250              // 100000 / 16 node-tiles (nodemlp)
#define MLP_WARPS 4

namespace {
struct EnvInit {
    EnvInit() { setenv("CUDA_MODULE_LOADING", "EAGER", 1); }
} env_init;
}

// ---------------- static device scratch --------------------------------------
// Feature mapping for xs rows: lane L holds features 2L and 2L+1.
__device__ __half2 g_xsh[NN * 32];        // xs rows packed half2 (12.8MB)
__device__ float  g_bufB[NN * HD];        // layer output (h1, then h2) fp32
__device__ float  g_ss[NN];               // xs @ att_src
__device__ float  g_sd[NN];               // xs @ att_dst
__device__ int    g_deg[NN];              // 1 + indegree
__device__ int    g_off[NN];              // segment base (unordered CSR)
__device__ int    g_cur[NN];
__device__ int    g_ecnt;                 // global edge-slot counter
__device__ uint2  g_edge[ETOT];           // {src, half2(se1,se2)} 8B records
__device__ float  g_m3[3];                // edge_attr column sums
__device__ float  g_we1[3];               // We1 @ ae1
__device__ float  g_we2[3];
__device__ float  g_emb[HD];

// ---------------- init (+ fused We@ae scalars in block 0) --------------------
__global__ void k_init(const float* __restrict__ We1, const float* __restrict__ ae1,
                       const float* __restrict__ We2, const float* __restrict__ ae2) {
    int i = blockIdx.x * blockDim.x + threadIdx.x;
    if (i < NN) g_deg[i] = 1;          // self loop
    if (i < HD) g_emb[i] = 0.f;
    if (i < 3)  g_m3[i] = 0.f;
    if (i == 0) g_ecnt = 0;
    if (blockIdx.x == 0) {
        int wid = threadIdx.x >> 5, lane = threadIdx.x & 31;
        if (wid >= 1 && wid <= 6) {
            int layer = (wid - 1) / 3, c = (wid - 1) % 3;
            const float* We = layer ? We2 : We1;
            const float* ae = layer ? ae2 : ae1;
            float s = We[c * HD + lane] * ae[lane] + We[c * HD + lane + 32] * ae[lane + 32];
            for (int o = 16; o; o >>= 1) s += __shfl_xor_sync(0xffffffffu, s, o);
            if (lane == 0) { if (layer) g_we2[c] = s; else g_we1[c] = s; }
        }
    }
}

// fused: edge_attr column sums + per-dst degree count (one pass over edges)
__global__ void k_edge_pre(const int* __restrict__ ei, const float* __restrict__ ea) {
    float s0 = 0.f, s1 = 0.f, s2 = 0.f;
    for (int e = blockIdx.x * blockDim.x + threadIdx.x; e < NE;
         e += gridDim.x * blockDim.x) {
        atomicAdd(&g_deg[ei[NE + e]], 1);
        s0 += ea[e * 3 + 0];
        s1 += ea[e * 3 + 1];
        s2 += ea[e * 3 + 2];
    }
    __shared__ float sb[3][256];
    int t = threadIdx.x;
    sb[0][t] = s0; sb[1][t] = s1; sb[2][t] = s2;
    __syncthreads();
    for (int st = 128; st; st >>= 1) {
        if (t < st) {
            sb[0][t] += sb[0][t + st];
            sb[1][t] += sb[1][t + st];
            sb[2][t] += sb[2][t + st];
        }
        __syncthreads();
    }
    if (t == 0) {
        atomicAdd(&g_m3[0], sb[0][0]);
        atomicAdd(&g_m3[1], sb[1][0]);
        atomicAdd(&g_m3[2], sb[2][0]);
    }
}

// ---------------- segment assignment: unordered CSR via atomic counter -------
__global__ void k_offsets() {
    int i = blockIdx.x * blockDim.x + threadIdx.x;
    if (i >= NN) return;
    int d = g_deg[i];
    int o = atomicAdd(&g_ecnt, d);
    g_off[i] = o;
    g_cur[i] = o + 1;                    // slot o = self loop
    const float inv = 1.0f / (float)NE;
    float m0 = g_m3[0] * inv, m1 = g_m3[1] * inv, m2 = g_m3[2] * inv;
    float se1 = m0 * g_we1[0] + m1 * g_we1[1] + m2 * g_we1[2];
    float se2 = m0 * g_we2[0] + m1 * g_we2[1] + m2 * g_we2[2];
    uint2 rec;
    rec.x = (unsigned)i;
    __half2 h = __floats2half2_rn(se1, se2);
    rec.y = *(unsigned*)&h;
    g_edge[o] = rec;
}

// ---------------- CSR scatter ------------------------------------------------
__global__ void k_scatter_edges(const int* __restrict__ ei,
                                const float* __restrict__ ea) {
    int e = blockIdx.x * blockDim.x + threadIdx.x;
    if (e >= NE) return;
    int s = ei[e], d = ei[NE + e];
    int pos = atomicAdd(&g_cur[d], 1);
    float a0 = ea[e * 3 + 0], a1 = ea[e * 3 + 1], a2 = ea[e * 3 + 2];
    float se1 = a0 * g_we1[0] + a1 * g_we1[1] + a2 * g_we1[2];
    float se2 = a0 * g_we2[0] + a1 * g_we2[1] + a2 * g_we2[2];
    uint2 rec;
    rec.x = (unsigned)s;
    __half2 h = __floats2half2_rn(se1, se2);
    rec.y = *(unsigned*)&h;
    g_edge[pos] = rec;
}

// ---------------- layer-1 node transform (K=13) ------------------------------
__global__ void k_gemm1(const float* __restrict__ in, const float* __restrict__ W,
                        const float* __restrict__ avec, const float* __restrict__ dvec) {
    __shared__ float Ws[FN * HD];
    for (int i = threadIdx.x; i < FN * HD; i += blockDim.x) Ws[i] = W[i];
    __syncthreads();
    int w = threadIdx.x >> 5, lane = threadIdx.x & 31;
    const float2* Wv = (const float2*)Ws;
    float2 av = ((const float2*)avec)[lane];
    float2 dv = ((const float2*)dvec)[lane];
    for (int v = blockIdx.x * 8 + w; v < NN; v += gridDim.x * 8) {
        float a0 = 0.f, a1 = 0.f;
        const float* row = in + (size_t)v * FN;
#pragma unroll
        for (int k = 0; k < FN; k++) {
            float xv = row[k];
            float2 wv = Wv[k * 32 + lane];
            a0 += xv * wv.x;
            a1 += xv * wv.y;
        }
        g_xsh[v * 32 + lane] = __floats2half2_rn(a0, a1);
        float ps = a0 * av.x + a1 * av.y;
        float pd = a0 * dv.x + a1 * dv.y;
        for (int o = 16; o; o >>= 1) {
            ps += __shfl_xor_sync(0xffffffffu, ps, o);
            pd += __shfl_xor_sync(0xffffffffu, pd, o);
        }
        if (lane == 0) { g_ss[v] = ps; g_sd[v] = pd; }
    }
}

// ---------------- layer-2 node transform: 8 nodes/warp register tile ---------
__global__ void k_gemm2(const float* __restrict__ W,
                        const float* __restrict__ avec, const float* __restrict__ dvec) {
    __shared__ float xb[8][8][HD];       // [warp][node][k]
    int w = threadIdx.x >> 5, lane = threadIdx.x & 31;
    int gw = blockIdx.x * 8 + w;
    int nwarps = gridDim.x * 8;
    const float2* Wv = (const float2*)W;
    float2 av = ((const float2*)avec)[lane];
    float2 dv = ((const float2*)dvec)[lane];
    for (int t = gw; t < NTASK; t += nwarps) {
        int v0 = t * 8;
#pragma unroll
        for (int n = 0; n < 8; n++) {
            xb[w][n][lane]      = g_bufB[(v0 + n) * HD + lane];
            xb[w][n][lane + 32] = g_bufB[(v0 + n) * HD + lane + 32];
        }
        __syncwarp();
        float acc0[8], acc1[8];
#pragma unroll
        for (int n = 0; n < 8; n++) { acc0[n] = 0.f; acc1[n] = 0.f; }
#pragma unroll 8
        for (int k = 0; k < HD; k++) {
            float2 wv = Wv[k * 32 + lane];
#pragma unroll
            for (int n = 0; n < 8; n++) {
                float xv = xb[w][n][k];
                acc0[n] += xv * wv.x;
                acc1[n] += xv * wv.y;
            }
        }
#pragma unroll
        for (int n = 0; n < 8; n++) {
            g_xsh[(v0 + n) * 32 + lane] = __floats2half2_rn(acc0[n], acc1[n]);
            float ps = acc0[n] * av.x + acc1[n] * av.y;
            float pd = acc0[n] * dv.x + acc1[n] * dv.y;
            for (int o = 16; o; o >>= 1) {
                ps += __shfl_xor_sync(0xffffffffu, ps, o);
                pd += __shfl_xor_sync(0xffffffffu, pd, o);
            }
            if (lane == 0) { g_ss[v0 + n] = ps; g_sd[v0 + n] = pd; }
        }
        __syncwarp();
    }
}

// ---------------- GAT aggregation: two-phase, warp per dst node --------------
template <int LAYER>
__global__ void k_gat(const float* __restrict__ bias) {
    int w = threadIdx.x >> 5, lane = threadIdx.x & 31;
    int v = blockIdx.x * 8 + w;          // grid covers exactly NN
    int beg = g_off[v];
    int cnt = g_deg[v];
    float sdv = g_sd[v];

    float den = 0.f, a0 = 0.f, a1 = 0.f;
    for (int base = 0; base < cnt; base += 32) {
        int m = cnt - base; if (m > 32) m = 32;
        float wt = 0.f; int s = 0;
        if (lane < m) {
            uint2 er = g_edge[beg + base + lane];
            s = (int)er.x;
            float2 se = __half22float2(*(__half2*)&er.y);
            float l = g_ss[s] + sdv + ((LAYER == 1) ? se.x : se.y);
            l = (l >= 0.f) ? l : SLOPE_GAT * l;
            wt = __expf(l);
        }
        den += wt;
#pragma unroll 8
        for (int j = 0; j < m; j++) {
            float wj = __shfl_sync(0xffffffffu, wt, j);
            int   sj = __shfl_sync(0xffffffffu, s, j);
            float2 xv = __half22float2(g_xsh[sj * 32 + lane]);
            a0 += wj * xv.x;
            a1 += wj * xv.y;
        }
    }
    for (int o = 16; o; o >>= 1) den += __shfl_xor_sync(0xffffffffu, den, o);
    float invden = 1.0f / (den + 1e-16f);
    float2 bv = ((const float2*)bias)[lane];
    float r0 = a0 * invden + bv.x;
    float r1 = a1 * invden + bv.y;
    if (LAYER == 1) { r0 = fmaxf(r0, 0.f); r1 = fmaxf(r1, 0.f); }
    ((float2*)g_bufB)[v * 32 + lane] = make_float2(r0, r1);
}

// ---------------- action head ------------------------------------------------
__global__ void k_action(const float* __restrict__ A1w, const float* __restrict__ A1b,
                         const float* __restrict__ A2w, const float* __restrict__ A2b,
                         float* __restrict__ out) {
    __shared__ float em[HD], a1[HD], a2[3];
    int t = threadIdx.x;
    em[t] = g_emb[t] * (1.0f / (float)NN);
    __syncthreads();
    float s = A1b[t];
    for (int k = 0; k < HD; k++) s += em[k] * A1w[k * HD + t];
    a1[t] = (s >= 0.f) ? s : SLOPE_MLP * s;
    __syncthreads();
    if (t < 3) {
        float s2 = A2b[t];
        for (int j = 0; j < HD; j++) s2 += a1[j] * A2w[j * 3 + t];
        a2[t] = (s2 >= 0.f) ? s2 : SLOPE_MLP * s2;
    }
    __syncthreads();
    if (t == 0) {
        float m = fmaxf(a2[0], fmaxf(a2[1], a2[2]));
        float e0 = __expf(a2[0] - m), e1 = __expf(a2[1] - m), e2 = __expf(a2[2] - m);
        float inv = 1.0f / (e0 + e1 + e2);
        out[0] = e0 * inv; out[1] = e1 * inv; out[2] = e2 * inv;
    }
}

// ---------------- node MLP: WMMA tensor-core, 16 nodes per warp --------------
// Layers 1+2 are 64x64 fp16 GEMMs (fp32 accumulate) on the tensor pipe.
// Bias + LeakyReLU applied via the lane->column mapping (lane L owns cols 2L, 2L+1).
// Fused graph-embedding partial sums on the h2 loads.
__global__ void k_nodemlp(const float* __restrict__ N1w, const float* __restrict__ N1b,
                          const float* __restrict__ N2w, const float* __restrict__ N2b,
                          const float* __restrict__ N3w, const float* __restrict__ N3b,
                          float* __restrict__ out) {
    __shared__ __half W1h[HD * HD];                 // 8KB
    __shared__ __half W2h[HD * HD];                 // 8KB
    __shared__ __half Ah[MLP_WARPS][16 * HD];       // 8KB: per-warp fp16 A tile
    __shared__ float  Cf[MLP_WARPS][16 * HD];       // 16KB: per-warp fp32 C tile
    __shared__ float  esum[MLP_WARPS][HD];          // 1KB
    int w = threadIdx.x >> 5, lane = threadIdx.x & 31;
    for (int i = threadIdx.x; i < HD * HD; i += blockDim.x) {
        W1h[i] = __float2half(N1w[i]);
        W2h[i] = __float2half(N2w[i]);
    }
    __syncthreads();
    float2 b1v = ((const float2*)N1b)[lane];
    float2 b2v = ((const float2*)N2b)[lane];
    float2 w3v = ((const float2*)N3w)[lane];
    float b3 = N3b[0];
    float e0 = 0.f, e1 = 0.f;
    int gw = blockIdx.x * MLP_WARPS + w;
    int nwarps = gridDim.x * MLP_WARPS;
    for (int t = gw; t < NT16; t += nwarps) {
        int v0 = t * 16;
        // load h2 tile, convert to fp16, accumulate emb partials
#pragma unroll
        for (int n = 0; n < 16; n++) {
            float2 hv = ((const float2*)g_bufB)[(v0 + n) * 32 + lane];
            e0 += hv.x; e1 += hv.y;
            *(__half2*)&Ah[w][n * HD + 2 * lane] = __floats2half2_rn(hv.x, hv.y);
        }
        __syncwarp();
        // layer 1: A(16x64) @ W1(64x64) -> Cf
#pragma unroll
        for (int nt = 0; nt < 4; nt++) {
            wmma::fragment<wmma::accumulator, 16, 16, 16, float> acc;
            wmma::fill_fragment(acc, 0.f);
#pragma unroll
            for (int kt = 0; kt < 4; kt++) {
                wmma::fragment<wmma::matrix_a, 16, 16, 16, __half, wmma::row_major> af;
                wmma::fragment<wmma::matrix_b, 16, 16, 16, __half, wmma::row_major> bf;
                wmma::load_matrix_sync(af, &Ah[w][kt * 16], HD);
                wmma::load_matrix_sync(bf, &W1h[kt * 16 * HD + nt * 16], HD);
                wmma::mma_sync(acc, af, bf, acc);
            }
            wmma::store_matrix_sync(&Cf[w][nt * 16], acc, HD, wmma::mem_row_major);
        }
        __syncwarp();
        // bias + lrelu -> fp16 A tile
#pragma unroll
        for (int n = 0; n < 16; n++) {
            float2 zv = *(float2*)&Cf[w][n * HD + 2 * lane];
            float z0 = zv.x + b1v.x; z0 = (z0 >= 0.f) ? z0 : SLOPE_MLP * z0;
            float z1 = zv.y + b1v.y; z1 = (z1 >= 0.f) ? z1 : SLOPE_MLP * z1;
            *(__half2*)&Ah[w][n * HD + 2 * lane] = __floats2half2_rn(z0, z1);
        }
        __syncwarp();
        // layer 2
#pragma unroll
        for (int nt = 0; nt < 4; nt++) {
            wmma::fragment<wmma::accumulator, 16, 16, 16, float> acc;
            wmma::fill_fragment(acc, 0.f);
#pragma unroll
            for (int kt = 0; kt < 4; kt++) {
                wmma::fragment<wmma::matrix_a, 16, 16, 16, __half, wmma::row_major> af;
                wmma::fragment<wmma::matrix_b, 16, 16, 16, __half, wmma::row_major> bf;
                wmma::load_matrix_sync(af, &Ah[w][kt * 16], HD);
                wmma::load_matrix_sync(bf, &W2h[kt * 16 * HD + nt * 16], HD);
                wmma::mma_sync(acc, af, bf, acc);
            }
            wmma::store_matrix_sync(&Cf[w][nt * 16], acc, HD, wmma::mem_row_major);
        }
        __syncwarp();
        // layer 3: bias2 + lrelu + dot(w3) + sigmoid
#pragma unroll
        for (int n = 0; n < 16; n++) {
            float2 zv = *(float2*)&Cf[w][n * HD + 2 * lane];
            float z0 = zv.x + b2v.x; z0 = (z0 >= 0.f) ? z0 : SLOPE_MLP * z0;
            float z1 = zv.y + b2v.y; z1 = (z1 >= 0.f) ? z1 : SLOPE_MLP * z1;
            float d = z0 * w3v.x + z1 * w3v.y;
            for (int o = 16; o; o >>= 1) d += __shfl_xor_sync(0xffffffffu, d, o);
            if (lane == 0) {
                float x = d + b3;
                out[3 + v0 + n] = 1.0f / (1.0f + __expf(-x));
            }
        }
        __syncwarp();
    }
    // block-level emb reduction -> 64 atomics per block
    esum[w][lane * 2]     = e0;
    esum[w][lane * 2 + 1] = e1;
    __syncthreads();
    if (w < 2) {
        int col = w * 32 + lane;
        float s = 0.f;
#pragma unroll
        for (int ww = 0; ww < MLP_WARPS; ww++) s += esum[ww][col];
        atomicAdd(&g_emb[col], s);
    }
}

// ---------------- launch -----------------------------------------------------
extern "C" void kernel_launch(void* const* d_in, const int* in_sizes, int n_in,
                              void* d_out, int out_size) {
    const float* x   = (const float*)d_in[0];
    const int*   ei  = (const int*)d_in[1];
    const float* ea  = (const float*)d_in[2];
    const float* W1  = (const float*)d_in[3];
    const float* We1 = (const float*)d_in[4];
    const float* as1 = (const float*)d_in[5];
    const float* ad1 = (const float*)d_in[6];
    const float* ae1 = (const float*)d_in[7];
    const float* b1  = (const float*)d_in[8];
    const float* W2  = (const float*)d_in[9];
    const float* We2 = (const float*)d_in[10];
    const float* as2 = (const float*)d_in[11];
    const float* ad2 = (const float*)d_in[12];
    const float* ae2 = (const float*)d_in[13];
    const float* b2  = (const float*)d_in[14];
    const float* A1w = (const float*)d_in[15];
    const float* A1b = (const float*)d_in[16];
    const float* A2w = (const float*)d_in[17];
    const float* A2b = (const float*)d_in[18];
    const float* N1w = (const float*)d_in[19];
    const float* N1b = (const float*)d_in[20];
    const float* N2w = (const float*)d_in[21];
    const float* N2b = (const float*)d_in[22];
    const float* N3w = (const float*)d_in[23];
    const float* N3b = (const float*)d_in[24];
    float* out = (float*)d_out;

    const int NB_N = (NN + 255) / 256;
    const int NB_E = (NE + 255) / 256;

    k_init<<<NB_N, 256>>>(We1, ae1, We2, ae2);
    k_edge_pre<<<1024, 256>>>(ei, ea);
    k_offsets<<<NB_N, 256>>>();
    k_scatter_edges<<<NB_E, 256>>>(ei, ea);

    // layer 1: x -> xsh -> bufB(h1, relu)
    k_gemm1<<<1184, 256>>>(x, W1, as1, ad1);
    k_gat<1><<<NTASK, 256>>>(b1);
    // layer 2: bufB(h1) -> xsh -> bufB(h2)
    k_gemm2<<<1563, 256>>>(W2, as2, ad2);
    k_gat<2><<<NTASK, 256>>>(b2);

    // heads (nodemlp also accumulates g_emb; action reads it afterwards)
    k_nodemlp<<<1563, 128>>>(N1w, N1b, N2w, N2b, N3w, N3b, out);
    k_action<<<1, 64>>>(A1w, A1b, A2w, A2b, out);
}

// round 12
// speedup vs baseline: 1.1076x; 1.1076x over previous
#include <cuda_runtime.h>
#include <cuda_fp16.h>
#include <stdlib.h>
#include <math.h>

#define NN 100000
#define NE 1600000
#define ETOT (NE + NN)
#define HD 64
#define FN 13
#define SLOPE_GAT 0.2f
#define SLOPE_MLP 0.01f
#define NG8 12500              // 100000 / 8 node-groups

namespace {
struct EnvInit {
    EnvInit() { setenv("CUDA_MODULE_LOADING", "EAGER", 1); }
} env_init;
}

// ---------------- static device scratch --------------------------------------
// Feature mapping for xs rows: lane L holds features 2L and 2L+1.
// Double-buffered across layers: layer-1 in g_xsh/g_ss/g_sd, layer-2 in *2.
// (The fused gat1+gemm2 kernel reads layer-1 buffers for arbitrary source
//  nodes while producing layer-2 values — writing in place would be a
//  cross-block WAR race, which is exactly what broke R11.)
__device__ __half2 g_xsh[NN * 32];        // xs1 rows packed half2 (12.8MB)
__device__ __half2 g_xsh2[NN * 32];       // xs2 rows (12.8MB)
__device__ float  g_ss[NN];               // xs1 @ att_src
__device__ float  g_sd[NN];               // xs1 @ att_dst
__device__ float  g_ss2[NN];              // xs2 @ att_src
__device__ float  g_sd2[NN];              // xs2 @ att_dst
__device__ int    g_deg[NN];              // 1 + indegree
__device__ int    g_off[NN];              // segment base (unordered CSR)
__device__ int    g_cur[NN];
__device__ int    g_ecnt;                 // global edge-slot counter
__device__ uint2  g_edge[ETOT];           // {src, half2(se1,se2)} 8B records
__device__ float  g_m3[3];                // edge_attr column sums
__device__ float  g_we1[3];               // We1 @ ae1
__device__ float  g_we2[3];
__device__ float  g_emb[HD];

// ---------------- init (+ fused We@ae scalars in block 0) --------------------
__global__ void k_init(const float* __restrict__ We1, const float* __restrict__ ae1,
                       const float* __restrict__ We2, const float* __restrict__ ae2) {
    int i = blockIdx.x * blockDim.x + threadIdx.x;
    if (i < NN) g_deg[i] = 1;          // self loop
    if (i < HD) g_emb[i] = 0.f;
    if (i < 3)  g_m3[i] = 0.f;
    if (i == 0) g_ecnt = 0;
    if (blockIdx.x == 0) {
        int wid = threadIdx.x >> 5, lane = threadIdx.x & 31;
        if (wid >= 1 && wid <= 6) {
            int layer = (wid - 1) / 3, c = (wid - 1) % 3;
            const float* We = layer ? We2 : We1;
            const float* ae = layer ? ae2 : ae1;
            float s = We[c * HD + lane] * ae[lane] + We[c * HD + lane + 32] * ae[lane + 32];
            for (int o = 16; o; o >>= 1) s += __shfl_xor_sync(0xffffffffu, s, o);
            if (lane == 0) { if (layer) g_we2[c] = s; else g_we1[c] = s; }
        }
    }
}

// fused: edge_attr column sums + per-dst degree count (one pass over edges)
__global__ void k_edge_pre(const int* __restrict__ ei, const float* __restrict__ ea) {
    float s0 = 0.f, s1 = 0.f, s2 = 0.f;
    for (int e = blockIdx.x * blockDim.x + threadIdx.x; e < NE;
         e += gridDim.x * blockDim.x) {
        atomicAdd(&g_deg[ei[NE + e]], 1);
        s0 += ea[e * 3 + 0];
        s1 += ea[e * 3 + 1];
        s2 += ea[e * 3 + 2];
    }
    __shared__ float sb[3][256];
    int t = threadIdx.x;
    sb[0][t] = s0; sb[1][t] = s1; sb[2][t] = s2;
    __syncthreads();
    for (int st = 128; st; st >>= 1) {
        if (t < st) {
            sb[0][t] += sb[0][t + st];
            sb[1][t] += sb[1][t + st];
            sb[2][t] += sb[2][t + st];
        }
        __syncthreads();
    }
    if (t == 0) {
        atomicAdd(&g_m3[0], sb[0][0]);
        atomicAdd(&g_m3[1], sb[1][0]);
        atomicAdd(&g_m3[2], sb[2][0]);
    }
}

// ---------------- segment assignment: unordered CSR via atomic counter -------
__global__ void k_offsets() {
    int i = blockIdx.x * blockDim.x + threadIdx.x;
    if (i >= NN) return;
    int d = g_deg[i];
    int o = atomicAdd(&g_ecnt, d);
    g_off[i] = o;
    g_cur[i] = o + 1;                    // slot o = self loop
    const float inv = 1.0f / (float)NE;
    float m0 = g_m3[0] * inv, m1 = g_m3[1] * inv, m2 = g_m3[2] * inv;
    float se1 = m0 * g_we1[0] + m1 * g_we1[1] + m2 * g_we1[2];
    float se2 = m0 * g_we2[0] + m1 * g_we2[1] + m2 * g_we2[2];
    uint2 rec;
    rec.x = (unsigned)i;
    __half2 h = __floats2half2_rn(se1, se2);
    rec.y = *(unsigned*)&h;
    g_edge[o] = rec;
}

// ---------------- CSR scatter ------------------------------------------------
__global__ void k_scatter_edges(const int* __restrict__ ei,
                                const float* __restrict__ ea) {
    int e = blockIdx.x * blockDim.x + threadIdx.x;
    if (e >= NE) return;
    int s = ei[e], d = ei[NE + e];
    int pos = atomicAdd(&g_cur[d], 1);
    float a0 = ea[e * 3 + 0], a1 = ea[e * 3 + 1], a2 = ea[e * 3 + 2];
    float se1 = a0 * g_we1[0] + a1 * g_we1[1] + a2 * g_we1[2];
    float se2 = a0 * g_we2[0] + a1 * g_we2[1] + a2 * g_we2[2];
    uint2 rec;
    rec.x = (unsigned)s;
    __half2 h = __floats2half2_rn(se1, se2);
    rec.y = *(unsigned*)&h;
    g_edge[pos] = rec;
}

// ---------------- layer-1 node transform (K=13) ------------------------------
__global__ void k_gemm1(const float* __restrict__ in, const float* __restrict__ W,
                        const float* __restrict__ avec, const float* __restrict__ dvec) {
    __shared__ float Ws[FN * HD];
    for (int i = threadIdx.x; i < FN * HD; i += blockDim.x) Ws[i] = W[i];
    __syncthreads();
    int w = threadIdx.x >> 5, lane = threadIdx.x & 31;
    const float2* Wv = (const float2*)Ws;
    float2 av = ((const float2*)avec)[lane];
    float2 dv = ((const float2*)dvec)[lane];
    for (int v = blockIdx.x * 8 + w; v < NN; v += gridDim.x * 8) {
        float a0 = 0.f, a1 = 0.f;
        const float* row = in + (size_t)v * FN;
#pragma unroll
        for (int k = 0; k < FN; k++) {
            float xv = row[k];
            float2 wv = Wv[k * 32 + lane];
            a0 += xv * wv.x;
            a1 += xv * wv.y;
        }
        g_xsh[v * 32 + lane] = __floats2half2_rn(a0, a1);
        float ps = a0 * av.x + a1 * av.y;
        float pd = a0 * dv.x + a1 * dv.y;
        for (int o = 16; o; o >>= 1) {
            ps += __shfl_xor_sync(0xffffffffu, ps, o);
            pd += __shfl_xor_sync(0xffffffffu, pd, o);
        }
        if (lane == 0) { g_ss[v] = ps; g_sd[v] = pd; }
    }
}

// ---- warp-level GAT aggregation of one node: returns (r0, r1) for lane ------
// lane L gets features 2L (r0) and 2L+1 (r1). Includes bias; no activation.
// LAYER selects which buffers/logit component to use.
template <int LAYER>
__device__ __forceinline__ void gat_node(int v, int lane, float2 bv,
                                         float& r0, float& r1) {
    const __half2* xsh = (LAYER == 1) ? g_xsh : g_xsh2;
    const float*   ss  = (LAYER == 1) ? g_ss  : g_ss2;
    const float*   sd  = (LAYER == 1) ? g_sd  : g_sd2;
    int beg = g_off[v];
    int cnt = g_deg[v];
    float sdv = sd[v];
    float den = 0.f, a0 = 0.f, a1 = 0.f;
    for (int base = 0; base < cnt; base += 32) {
        int m = cnt - base; if (m > 32) m = 32;
        float wt = 0.f; int s = 0;
        if (lane < m) {
            uint2 er = g_edge[beg + base + lane];
            s = (int)er.x;
            float2 se = __half22float2(*(__half2*)&er.y);
            float l = ss[s] + sdv + ((LAYER == 1) ? se.x : se.y);
            l = (l >= 0.f) ? l : SLOPE_GAT * l;
            wt = __expf(l);
        }
        den += wt;
#pragma unroll 8
        for (int j = 0; j < m; j++) {
            float wj = __shfl_sync(0xffffffffu, wt, j);
            int   sj = __shfl_sync(0xffffffffu, s, j);
            float2 xv = __half22float2(xsh[sj * 32 + lane]);
            a0 += wj * xv.x;
            a1 += wj * xv.y;
        }
    }
    for (int o = 16; o; o >>= 1) den += __shfl_xor_sync(0xffffffffu, den, o);
    float invden = 1.0f / (den + 1e-16f);
    r0 = a0 * invden + bv.x;
    r1 = a1 * invden + bv.y;
}

// ---------------- fused: GAT layer1 + relu + W2 transform + ss2/sd2 ----------
// Reads layer-1 buffers (read-only here), writes layer-2 buffers (disjoint).
__global__ void k_gat1_gemm2(const float* __restrict__ bias1,
                             const float* __restrict__ W2,
                             const float* __restrict__ avec, const float* __restrict__ dvec) {
    __shared__ float xb[8][8][HD];       // [warp][node][feature]
    int w = threadIdx.x >> 5, lane = threadIdx.x & 31;
    int gw = blockIdx.x * 8 + w;
    if (gw >= NG8) return;
    int v0 = gw * 8;
    float2 b1 = ((const float2*)bias1)[lane];
    const float2* Wv = (const float2*)W2;
    float2 av = ((const float2*)avec)[lane];
    float2 dv = ((const float2*)dvec)[lane];

#pragma unroll
    for (int n = 0; n < 8; n++) {
        float r0, r1;
        gat_node<1>(v0 + n, lane, b1, r0, r1);
        xb[w][n][lane * 2]     = fmaxf(r0, 0.f);     // relu (layer1)
        xb[w][n][lane * 2 + 1] = fmaxf(r1, 0.f);
    }
    __syncwarp();
    float acc0[8], acc1[8];
#pragma unroll
    for (int n = 0; n < 8; n++) { acc0[n] = 0.f; acc1[n] = 0.f; }
#pragma unroll 8
    for (int k = 0; k < HD; k++) {
        float2 wv = Wv[k * 32 + lane];
#pragma unroll
        for (int n = 0; n < 8; n++) {
            float xv = xb[w][n][k];
            acc0[n] += xv * wv.x;
            acc1[n] += xv * wv.y;
        }
    }
#pragma unroll
    for (int n = 0; n < 8; n++) {
        g_xsh2[(v0 + n) * 32 + lane] = __floats2half2_rn(acc0[n], acc1[n]);
        float ps = acc0[n] * av.x + acc1[n] * av.y;
        float pd = acc0[n] * dv.x + acc1[n] * dv.y;
        for (int o = 16; o; o >>= 1) {
            ps += __shfl_xor_sync(0xffffffffu, ps, o);
            pd += __shfl_xor_sync(0xffffffffu, pd, o);
        }
        if (lane == 0) { g_ss2[v0 + n] = ps; g_sd2[v0 + n] = pd; }
    }
}

// ---------------- fused: GAT layer2 + node MLP + emb partials ----------------
__global__ void k_gat2_mlp(const float* __restrict__ bias2,
                           const float* __restrict__ N1w, const float* __restrict__ N1b,
                           const float* __restrict__ N2w, const float* __restrict__ N2b,
                           const float* __restrict__ N3w, const float* __restrict__ N3b,
                           float* __restrict__ out) {
    __shared__ float xb[8][8][HD];       // reused for h2 then z
    __shared__ float esum[8][HD];
    int w = threadIdx.x >> 5, lane = threadIdx.x & 31;
    int gw = blockIdx.x * 8 + w;
    float2 b2g = ((const float2*)bias2)[lane];
    const float2* W1v = (const float2*)N1w;
    const float2* W2v = (const float2*)N2w;
    float2 b1v = ((const float2*)N1b)[lane];
    float2 b2v = ((const float2*)N2b)[lane];
    float2 w3v = ((const float2*)N3w)[lane];
    float b3 = N3b[0];
    float e0 = 0.f, e1 = 0.f;

    if (gw < NG8) {
        int v0 = gw * 8;
#pragma unroll
        for (int n = 0; n < 8; n++) {
            float r0, r1;
            gat_node<2>(v0 + n, lane, b2g, r0, r1);
            e0 += r0; e1 += r1;                       // emb partials (h2)
            xb[w][n][lane * 2]     = r0;
            xb[w][n][lane * 2 + 1] = r1;
        }
        __syncwarp();
        // MLP layer 1
        float acc0[8], acc1[8];
#pragma unroll
        for (int n = 0; n < 8; n++) { acc0[n] = b1v.x; acc1[n] = b1v.y; }
#pragma unroll 8
        for (int k = 0; k < HD; k++) {
            float2 wv = W1v[k * 32 + lane];
#pragma unroll
            for (int n = 0; n < 8; n++) {
                float xv = xb[w][n][k];
                acc0[n] += xv * wv.x;
                acc1[n] += xv * wv.y;
            }
        }
        __syncwarp();
#pragma unroll
        for (int n = 0; n < 8; n++) {
            float z0 = (acc0[n] >= 0.f) ? acc0[n] : SLOPE_MLP * acc0[n];
            float z1 = (acc1[n] >= 0.f) ? acc1[n] : SLOPE_MLP * acc1[n];
            xb[w][n][lane * 2]     = z0;
            xb[w][n][lane * 2 + 1] = z1;
        }
        __syncwarp();
        // MLP layer 2
#pragma unroll
        for (int n = 0; n < 8; n++) { acc0[n] = b2v.x; acc1[n] = b2v.y; }
#pragma unroll 8
        for (int k = 0; k < HD; k++) {
            float2 wv = W2v[k * 32 + lane];
#pragma unroll
            for (int n = 0; n < 8; n++) {
                float zv = xb[w][n][k];
                acc0[n] += zv * wv.x;
                acc1[n] += zv * wv.y;
            }
        }
        // layer 3 + sigmoid
#pragma unroll
        for (int n = 0; n < 8; n++) {
            float z0 = (acc0[n] >= 0.f) ? acc0[n] : SLOPE_MLP * acc0[n];
            float z1 = (acc1[n] >= 0.f) ? acc1[n] : SLOPE_MLP * acc1[n];
            float d = z0 * w3v.x + z1 * w3v.y;
            for (int o = 16; o; o >>= 1) d += __shfl_xor_sync(0xffffffffu, d, o);
            if (lane == 0) {
                float x = d + b3;
                out[3 + v0 + n] = 1.0f / (1.0f + __expf(-x));
            }
        }
    }
    // block-level emb reduction -> 64 atomics per block
    esum[w][lane * 2]     = e0;
    esum[w][lane * 2 + 1] = e1;
    __syncthreads();
    if (w < 2) {
        int col = w * 32 + lane;
        float s = 0.f;
#pragma unroll
        for (int ww = 0; ww < 8; ww++) s += esum[ww][col];
        atomicAdd(&g_emb[col], s);
    }
}

// ---------------- action head ------------------------------------------------
__global__ void k_action(const float* __restrict__ A1w, const float* __restrict__ A1b,
                         const float* __restrict__ A2w, const float* __restrict__ A2b,
                         float* __restrict__ out) {
    __shared__ float em[HD], a1[HD], a2[3];
    int t = threadIdx.x;
    em[t] = g_emb[t] * (1.0f / (float)NN);
    __syncthreads();
    float s = A1b[t];
    for (int k = 0; k < HD; k++) s += em[k] * A1w[k * HD + t];
    a1[t] = (s >= 0.f) ? s : SLOPE_MLP * s;
    __syncthreads();
    if (t < 3) {
        float s2 = A2b[t];
        for (int j = 0; j < HD; j++) s2 += a1[j] * A2w[j * 3 + t];
        a2[t] = (s2 >= 0.f) ? s2 : SLOPE_MLP * s2;
    }
    __syncthreads();
    if (t == 0) {
        float m = fmaxf(a2[0], fmaxf(a2[1], a2[2]));
        float e0 = __expf(a2[0] - m), e1 = __expf(a2[1] - m), e2 = __expf(a2[2] - m);
        float inv = 1.0f / (e0 + e1 + e2);
        out[0] = e0 * inv; out[1] = e1 * inv; out[2] = e2 * inv;
    }
}

// ---------------- launch -----------------------------------------------------
extern "C" void kernel_launch(void* const* d_in, const int* in_sizes, int n_in,
                              void* d_out, int out_size) {
    const float* x   = (const float*)d_in[0];
    const int*   ei  = (const int*)d_in[1];
    const float* ea  = (const float*)d_in[2];
    const float* W1  = (const float*)d_in[3];
    const float* We1 = (const float*)d_in[4];
    const float* as1 = (const float*)d_in[5];
    const float* ad1 = (const float*)d_in[6];
    const float* ae1 = (const float*)d_in[7];
    const float* b1  = (const float*)d_in[8];
    const float* W2  = (const float*)d_in[9];
    const float* We2 = (const float*)d_in[10];
    const float* as2 = (const float*)d_in[11];
    const float* ad2 = (const float*)d_in[12];
    const float* ae2 = (const float*)d_in[13];
    const float* b2  = (const float*)d_in[14];
    const float* A1w = (const float*)d_in[15];
    const float* A1b = (const float*)d_in[16];
    const float* A2w = (const float*)d_in[17];
    const float* A2b = (const float*)d_in[18];
    const float* N1w = (const float*)d_in[19];
    const float* N1b = (const float*)d_in[20];
    const float* N2w = (const float*)d_in[21];
    const float* N2b = (const float*)d_in[22];
    const float* N3w = (const float*)d_in[23];
    const float* N3b = (const float*)d_in[24];
    float* out = (float*)d_out;

    const int NB_N = (NN + 255) / 256;
    const int NB_E = (NE + 255) / 256;
    const int NB_G = (NG8 + 7) / 8;      // 1563

    k_init<<<NB_N, 256>>>(We1, ae1, We2, ae2);
    k_edge_pre<<<1024, 256>>>(ei, ea);
    k_offsets<<<NB_N, 256>>>();
    k_scatter_edges<<<NB_E, 256>>>(ei, ea);

    // layer 1 transform
    k_gemm1<<<1184, 256>>>(x, W1, as1, ad1);
    // fused: gat1 + relu + W2 transform (reads layer-1 bufs, writes layer-2 bufs)
    k_gat1_gemm2<<<NB_G, 256>>>(b1, W2, as2, ad2);
    // fused: gat2 + node MLP + emb partials
    k_gat2_mlp<<<NB_G, 256>>>(b2, N1w, N1b, N2w, N2b, N3w, N3b, out);
    // action head (reads g_emb)
    k_action<<<1, 64>>>(A1w, A1b, A2w, A2b, out);
}

// round 13
// speedup vs baseline: 1.1794x; 1.0648x over previous
#include <cuda_runtime.h>
#include <cuda_fp16.h>
#include <stdlib.h>
#include <math.h>

#define NN 100000
#define NE 1600000
#define ETOT (NE + NN)
#define HD 64
#define FN 13
#define SLOPE_GAT 0.2f
#define SLOPE_MLP 0.01f
#define NTASK 12500            // 100000 / 8 node-groups

#define PRE_BLOCKS 1024        // edge_pre portion of the fat kernel
#define G1_BLOCKS 1184         // gemm1 portion
#define G1_WARPS (G1_BLOCKS * 8)

namespace {
struct EnvInit {
    EnvInit() { setenv("CUDA_MODULE_LOADING", "EAGER", 1); }
} env_init;
}

// ---------------- static device scratch --------------------------------------
// Feature mapping for xs rows: lane L holds features 2L and 2L+1.
__device__ __half2 g_xsh[NN * 32];        // xs rows packed half2 (12.8MB)
__device__ float  g_bufB[NN * HD];        // layer output (h1, then h2) fp32
__device__ float  g_ss[NN];               // xs @ att_src
__device__ float  g_sd[NN];               // xs @ att_dst
__device__ int    g_deg[NN];              // 1 + indegree
__device__ int    g_off[NN];              // segment base (unordered CSR)
__device__ int    g_cur[NN];
__device__ int    g_ecnt;                 // global edge-slot counter
__device__ uint2  g_edge[ETOT];           // {src, half2(se1,se2)} 8B records
__device__ float  g_m3[3];                // edge_attr column sums
__device__ float  g_we1[3];               // We1 @ ae1
__device__ float  g_we2[3];
__device__ float  g_emb[HD];

// ---------------- init (+ fused We@ae scalars in block 0) --------------------
__global__ void k_init(const float* __restrict__ We1, const float* __restrict__ ae1,
                       const float* __restrict__ We2, const float* __restrict__ ae2) {
    int i = blockIdx.x * blockDim.x + threadIdx.x;
    if (i < NN) g_deg[i] = 1;          // self loop
    if (i < HD) g_emb[i] = 0.f;
    if (i < 3)  g_m3[i] = 0.f;
    if (i == 0) g_ecnt = 0;
    if (blockIdx.x == 0) {
        int wid = threadIdx.x >> 5, lane = threadIdx.x & 31;
        if (wid >= 1 && wid <= 6) {
            int layer = (wid - 1) / 3, c = (wid - 1) % 3;
            const float* We = layer ? We2 : We1;
            const float* ae = layer ? ae2 : ae1;
            float s = We[c * HD + lane] * ae[lane] + We[c * HD + lane + 32] * ae[lane + 32];
            for (int o = 16; o; o >>= 1) s += __shfl_xor_sync(0xffffffffu, s, o);
            if (lane == 0) { if (layer) g_we2[c] = s; else g_we1[c] = s; }
        }
    }
}

// ---------------- FAT kernel: edge preprocessing || layer-1 transform --------
// Blocks [0, PRE_BLOCKS): edge_attr column sums + per-dst degree count.
// Blocks [PRE_BLOCKS, PRE_BLOCKS+G1_BLOCKS): gemm1 (x @ W1 -> xsh, ss, sd).
// The two are data-independent; co-running hides gemm1 under the edge pass.
__global__ void k_pre(const int* __restrict__ ei, const float* __restrict__ ea,
                      const float* __restrict__ x, const float* __restrict__ W1,
                      const float* __restrict__ avec, const float* __restrict__ dvec) {
    __shared__ float sb[3][256];
    __shared__ float Ws[FN * HD];
    int t = threadIdx.x;
    if (blockIdx.x < PRE_BLOCKS) {
        // ---- edge_pre path ----
        float s0 = 0.f, s1 = 0.f, s2 = 0.f;
        for (int e = blockIdx.x * blockDim.x + t; e < NE;
             e += PRE_BLOCKS * blockDim.x) {
            atomicAdd(&g_deg[ei[NE + e]], 1);
            s0 += ea[e * 3 + 0];
            s1 += ea[e * 3 + 1];
            s2 += ea[e * 3 + 2];
        }
        sb[0][t] = s0; sb[1][t] = s1; sb[2][t] = s2;
        __syncthreads();
        for (int st = 128; st; st >>= 1) {
            if (t < st) {
                sb[0][t] += sb[0][t + st];
                sb[1][t] += sb[1][t + st];
                sb[2][t] += sb[2][t + st];
            }
            __syncthreads();
        }
        if (t == 0) {
            atomicAdd(&g_m3[0], sb[0][0]);
            atomicAdd(&g_m3[1], sb[1][0]);
            atomicAdd(&g_m3[2], sb[2][0]);
        }
    } else {
        // ---- gemm1 path ----
        for (int i = t; i < FN * HD; i += blockDim.x) Ws[i] = W1[i];
        __syncthreads();
        int w = t >> 5, lane = t & 31;
        const float2* Wv = (const float2*)Ws;
        float2 av = ((const float2*)avec)[lane];
        float2 dv = ((const float2*)dvec)[lane];
        int gw = (blockIdx.x - PRE_BLOCKS) * 8 + w;
        for (int v = gw; v < NN; v += G1_WARPS) {
            float a0 = 0.f, a1 = 0.f;
            const float* row = x + (size_t)v * FN;
#pragma unroll
            for (int k = 0; k < FN; k++) {
                float xv = row[k];
                float2 wv = Wv[k * 32 + lane];
                a0 += xv * wv.x;
                a1 += xv * wv.y;
            }
            g_xsh[v * 32 + lane] = __floats2half2_rn(a0, a1);
            float ps = a0 * av.x + a1 * av.y;
            float pd = a0 * dv.x + a1 * dv.y;
            for (int o = 16; o; o >>= 1) {
                ps += __shfl_xor_sync(0xffffffffu, ps, o);
                pd += __shfl_xor_sync(0xffffffffu, pd, o);
            }
            if (lane == 0) { g_ss[v] = ps; g_sd[v] = pd; }
        }
    }
}

// ---------------- segment assignment: unordered CSR via atomic counter -------
__global__ void k_offsets() {
    int i = blockIdx.x * blockDim.x + threadIdx.x;
    if (i >= NN) return;
    int d = g_deg[i];
    int o = atomicAdd(&g_ecnt, d);
    g_off[i] = o;
    g_cur[i] = o + 1;                    // slot o = self loop
    const float inv = 1.0f / (float)NE;
    float m0 = g_m3[0] * inv, m1 = g_m3[1] * inv, m2 = g_m3[2] * inv;
    float se1 = m0 * g_we1[0] + m1 * g_we1[1] + m2 * g_we1[2];
    float se2 = m0 * g_we2[0] + m1 * g_we2[1] + m2 * g_we2[2];
    uint2 rec;
    rec.x = (unsigned)i;
    __half2 h = __floats2half2_rn(se1, se2);
    rec.y = *(unsigned*)&h;
    g_edge[o] = rec;
}

// ---------------- CSR scatter ------------------------------------------------
__global__ void k_scatter_edges(const int* __restrict__ ei,
                                const float* __restrict__ ea) {
    int e = blockIdx.x * blockDim.x + threadIdx.x;
    if (e >= NE) return;
    int s = ei[e], d = ei[NE + e];
    int pos = atomicAdd(&g_cur[d], 1);
    float a0 = ea[e * 3 + 0], a1 = ea[e * 3 + 1], a2 = ea[e * 3 + 2];
    float se1 = a0 * g_we1[0] + a1 * g_we1[1] + a2 * g_we1[2];
    float se2 = a0 * g_we2[0] + a1 * g_we2[1] + a2 * g_we2[2];
    uint2 rec;
    rec.x = (unsigned)s;
    __half2 h = __floats2half2_rn(se1, se2);
    rec.y = *(unsigned*)&h;
    g_edge[pos] = rec;
}

// ---------------- layer-2 node transform: 8 nodes/warp register tile ---------
__global__ void k_gemm2(const float* __restrict__ W,
                        const float* __restrict__ avec, const float* __restrict__ dvec) {
    __shared__ float xb[8][8][HD];       // [warp][node][k]
    int w = threadIdx.x >> 5, lane = threadIdx.x & 31;
    int gw = blockIdx.x * 8 + w;
    int nwarps = gridDim.x * 8;
    const float2* Wv = (const float2*)W;
    float2 av = ((const float2*)avec)[lane];
    float2 dv = ((const float2*)dvec)[lane];
    for (int t = gw; t < NTASK; t += nwarps) {
        int v0 = t * 8;
#pragma unroll
        for (int n = 0; n < 8; n++) {
            xb[w][n][lane]      = g_bufB[(v0 + n) * HD + lane];
            xb[w][n][lane + 32] = g_bufB[(v0 + n) * HD + lane + 32];
        }
        __syncwarp();
        float acc0[8], acc1[8];
#pragma unroll
        for (int n = 0; n < 8; n++) { acc0[n] = 0.f; acc1[n] = 0.f; }
#pragma unroll 8
        for (int k = 0; k < HD; k++) {
            float2 wv = Wv[k * 32 + lane];
#pragma unroll
            for (int n = 0; n < 8; n++) {
                float xv = xb[w][n][k];
                acc0[n] += xv * wv.x;
                acc1[n] += xv * wv.y;
            }
        }
#pragma unroll
        for (int n = 0; n < 8; n++) {
            g_xsh[(v0 + n) * 32 + lane] = __floats2half2_rn(acc0[n], acc1[n]);
            float ps = acc0[n] * av.x + acc1[n] * av.y;
            float pd = acc0[n] * dv.x + acc1[n] * dv.y;
            for (int o = 16; o; o >>= 1) {
                ps += __shfl_xor_sync(0xffffffffu, ps, o);
                pd += __shfl_xor_sync(0xffffffffu, pd, o);
            }
            if (lane == 0) { g_ss[v0 + n] = ps; g_sd[v0 + n] = pd; }
        }
        __syncwarp();
    }
}

// ---------------- GAT aggregation: two-phase, warp per dst node --------------
template <int LAYER>
__global__ void k_gat(const float* __restrict__ bias) {
    int w = threadIdx.x >> 5, lane = threadIdx.x & 31;
    int v = blockIdx.x * 8 + w;          // grid covers exactly NN
    int beg = g_off[v];
    int cnt = g_deg[v];
    float sdv = g_sd[v];

    float den = 0.f, a0 = 0.f, a1 = 0.f;
    for (int base = 0; base < cnt; base += 32) {
        int m = cnt - base; if (m > 32) m = 32;
        float wt = 0.f; int s = 0;
        if (lane < m) {
            uint2 er = g_edge[beg + base + lane];
            s = (int)er.x;
            float2 se = __half22float2(*(__half2*)&er.y);
            float l = g_ss[s] + sdv + ((LAYER == 1) ? se.x : se.y);
            l = (l >= 0.f) ? l : SLOPE_GAT * l;
            wt = __expf(l);
        }
        den += wt;
#pragma unroll 8
        for (int j = 0; j < m; j++) {
            float wj = __shfl_sync(0xffffffffu, wt, j);
            int   sj = __shfl_sync(0xffffffffu, s, j);
            float2 xv = __half22float2(g_xsh[sj * 32 + lane]);
            a0 += wj * xv.x;
            a1 += wj * xv.y;
        }
    }
    for (int o = 16; o; o >>= 1) den += __shfl_xor_sync(0xffffffffu, den, o);
    float invden = 1.0f / (den + 1e-16f);
    float2 bv = ((const float2*)bias)[lane];
    float r0 = a0 * invden + bv.x;
    float r1 = a1 * invden + bv.y;
    if (LAYER == 1) { r0 = fmaxf(r0, 0.f); r1 = fmaxf(r1, 0.f); }
    ((float2*)g_bufB)[v * 32 + lane] = make_float2(r0, r1);
}

// ---------------- action head ------------------------------------------------
__global__ void k_action(const float* __restrict__ A1w, const float* __restrict__ A1b,
                         const float* __restrict__ A2w, const float* __restrict__ A2b,
                         float* __restrict__ out) {
    __shared__ float em[HD], a1[HD], a2[3];
    int t = threadIdx.x;
    em[t] = g_emb[t] * (1.0f / (float)NN);
    __syncthreads();
    float s = A1b[t];
    for (int k = 0; k < HD; k++) s += em[k] * A1w[k * HD + t];
    a1[t] = (s >= 0.f) ? s : SLOPE_MLP * s;
    __syncthreads();
    if (t < 3) {
        float s2 = A2b[t];
        for (int j = 0; j < HD; j++) s2 += a1[j] * A2w[j * 3 + t];
        a2[t] = (s2 >= 0.f) ? s2 : SLOPE_MLP * s2;
    }
    __syncthreads();
    if (t == 0) {
        float m = fmaxf(a2[0], fmaxf(a2[1], a2[2]));
        float e0 = __expf(a2[0] - m), e1 = __expf(a2[1] - m), e2 = __expf(a2[2] - m);
        float inv = 1.0f / (e0 + e1 + e2);
        out[0] = e0 * inv; out[1] = e1 * inv; out[2] = e2 * inv;
    }
}

// ---------------- node MLP + fused graph-embedding partial sums --------------
__global__ void k_nodemlp(const float* __restrict__ N1w, const float* __restrict__ N1b,
                          const float* __restrict__ N2w, const float* __restrict__ N2b,
                          const float* __restrict__ N3w, const float* __restrict__ N3b,
                          float* __restrict__ out) {
    __shared__ float xb[8][8][HD];       // reused for h then z
    __shared__ float esum[8][HD];        // per-warp emb partials
    int w = threadIdx.x >> 5, lane = threadIdx.x & 31;
    int gw = blockIdx.x * 8 + w;
    int nwarps = gridDim.x * 8;
    const float2* W1v = (const float2*)N1w;
    const float2* W2v = (const float2*)N2w;
    float2 b1v = ((const float2*)N1b)[lane];
    float2 b2v = ((const float2*)N2b)[lane];
    float2 w3v = ((const float2*)N3w)[lane];
    float b3 = N3b[0];
    float e0 = 0.f, e1 = 0.f;            // emb partials (features 2L, 2L+1)
    for (int t = gw; t < NTASK; t += nwarps) {
        int v0 = t * 8;
#pragma unroll
        for (int n = 0; n < 8; n++) {
            float2 hv = ((const float2*)g_bufB)[(v0 + n) * 32 + lane];
            e0 += hv.x; e1 += hv.y;
            xb[w][n][lane * 2]     = hv.x;
            xb[w][n][lane * 2 + 1] = hv.y;
        }
        __syncwarp();
        // layer 1 (lane produces features 2L, 2L+1)
        float acc0[8], acc1[8];
#pragma unroll
        for (int n = 0; n < 8; n++) { acc0[n] = b1v.x; acc1[n] = b1v.y; }
#pragma unroll 8
        for (int k = 0; k < HD; k++) {
            float2 wv = W1v[k * 32 + lane];
#pragma unroll
            for (int n = 0; n < 8; n++) {
                float xv = xb[w][n][k];
                acc0[n] += xv * wv.x;
                acc1[n] += xv * wv.y;
            }
        }
        __syncwarp();       // all reads of xb done before overwrite
#pragma unroll
        for (int n = 0; n < 8; n++) {
            float z0 = (acc0[n] >= 0.f) ? acc0[n] : SLOPE_MLP * acc0[n];
            float z1 = (acc1[n] >= 0.f) ? acc1[n] : SLOPE_MLP * acc1[n];
            xb[w][n][lane * 2]     = z0;
            xb[w][n][lane * 2 + 1] = z1;
        }
        __syncwarp();
        // layer 2
#pragma unroll
        for (int n = 0; n < 8; n++) { acc0[n] = b2v.x; acc1[n] = b2v.y; }
#pragma unroll 8
        for (int k = 0; k < HD; k++) {
            float2 wv = W2v[k * 32 + lane];
#pragma unroll
            for (int n = 0; n < 8; n++) {
                float zv = xb[w][n][k];
                acc0[n] += zv * wv.x;
                acc1[n] += zv * wv.y;
            }
        }
        // layer 3 + sigmoid
#pragma unroll
        for (int n = 0; n < 8; n++) {
            float z0 = (acc0[n] >= 0.f) ? acc0[n] : SLOPE_MLP * acc0[n];
            float z1 = (acc1[n] >= 0.f) ? acc1[n] : SLOPE_MLP * acc1[n];
            float d = z0 * w3v.x + z1 * w3v.y;
            for (int o = 16; o; o >>= 1) d += __shfl_xor_sync(0xffffffffu, d, o);
            if (lane == 0) {
                float x = d + b3;
                out[3 + v0 + n] = 1.0f / (1.0f + __expf(-x));
            }
        }
        __syncwarp();
    }
    // block-level emb reduction -> 64 atomics per block
    esum[w][lane * 2]     = e0;
    esum[w][lane * 2 + 1] = e1;
    __syncthreads();
    if (w < 2) {
        int col = w * 32 + lane;
        float s = 0.f;
#pragma unroll
        for (int ww = 0; ww < 8; ww++) s += esum[ww][col];
        atomicAdd(&g_emb[col], s);
    }
}

// ---------------- launch -----------------------------------------------------
extern "C" void kernel_launch(void* const* d_in, const int* in_sizes, int n_in,
                              void* d_out, int out_size) {
    const float* x   = (const float*)d_in[0];
    const int*   ei  = (const int*)d_in[1];
    const float* ea  = (const float*)d_in[2];
    const float* W1  = (const float*)d_in[3];
    const float* We1 = (const float*)d_in[4];
    const float* as1 = (const float*)d_in[5];
    const float* ad1 = (const float*)d_in[6];
    const float* ae1 = (const float*)d_in[7];
    const float* b1  = (const float*)d_in[8];
    const float* W2  = (const float*)d_in[9];
    const float* We2 = (const float*)d_in[10];
    const float* as2 = (const float*)d_in[11];
    const float* ad2 = (const float*)d_in[12];
    const float* ae2 = (const float*)d_in[13];
    const float* b2  = (const float*)d_in[14];
    const float* A1w = (const float*)d_in[15];
    const float* A1b = (const float*)d_in[16];
    const float* A2w = (const float*)d_in[17];
    const float* A2b = (const float*)d_in[18];
    const float* N1w = (const float*)d_in[19];
    const float* N1b = (const float*)d_in[20];
    const float* N2w = (const float*)d_in[21];
    const float* N2b = (const float*)d_in[22];
    const float* N3w = (const float*)d_in[23];
    const float* N3b = (const float*)d_in[24];
    float* out = (float*)d_out;

    const int NB_N = (NN + 255) / 256;
    const int NB_E = (NE + 255) / 256;

    k_init<<<NB_N, 256>>>(We1, ae1, We2, ae2);
    // fat kernel: edge_pre (deg + ea sums) || gemm1 (xs1, ss1, sd1)
    k_pre<<<PRE_BLOCKS + G1_BLOCKS, 256>>>(ei, ea, x, W1, as1, ad1);
    k_offsets<<<NB_N, 256>>>();
    k_scatter_edges<<<NB_E, 256>>>(ei, ea);

    // layer 1 aggregation
    k_gat<1><<<NTASK, 256>>>(b1);
    // layer 2: bufB(h1) -> xsh -> bufB(h2)
    k_gemm2<<<1563, 256>>>(W2, as2, ad2);
    k_gat<2><<<NTASK, 256>>>(b2);

    // heads (nodemlp also accumulates g_emb; action reads it afterwards)
    k_nodemlp<<<1563, 256>>>(N1w, N1b, N2w, N2b, N3w, N3b, out);
    k_action<<<1, 64>>>(A1w, A1b, A2w, A2b, out);
}